// round 2
// baseline (speedup 1.0000x reference)
#include <cuda_runtime.h>
#include <cstdint>

#define Bdim 256
#define Udim 512
#define Ddim 512
#define N4U  2048

// ---------------- scratch ----------------
__device__ float g_pre [Bdim * N4U];        // gates pre-activations [B, 4U]
__device__ float g_hw  [Bdim * Udim];       // h_tm1 @ w
__device__ float g_red4[Bdim * 4 * Udim];   // partial hebb reductions (4 u-chunks)
__device__ float g_g   [Bdim * Udim];       // eta[b,v]*itc[b,v]

// =======================================================================
// Phase 1: one kernel, three block families (256 threads each):
//   [0, 1024)      : hebb partial reduce  (b = bid>>2, u-chunk = bid&3)
//   [1024, 1152)   : gates GEMM  pre = bias + x@kernel (+ h@rec except c-slice)
//   [1152, 1184)   : hw GEMM     hw = h_tm1 @ w
// =======================================================================

__device__ __forceinline__ void gemm64(
    const float* __restrict__ A1, const float* __restrict__ B1,
    const float* __restrict__ A2, const float* __restrict__ B2,
    const float* __restrict__ bias, float* __restrict__ C,
    int N, int m0, int n0, bool do_rec, bool add_bias, float* smem)
{
    const int K = 512;
    float (*As)[64] = (float(*)[64])smem;          // 16x64
    float (*Bs)[64] = (float(*)[64])(smem + 1024); // 16x64

    int tid = threadIdx.x;
    int tx  = tid & 15;
    int ty  = tid >> 4;

    float acc[4][4];
    #pragma unroll
    for (int p = 0; p < 4; ++p)
        #pragma unroll
        for (int q = 0; q < 4; ++q) acc[p][q] = 0.f;

    int npass = do_rec ? 2 : 1;
    for (int pass = 0; pass < npass; ++pass) {
        const float* A = pass ? A2 : A1;   // [256, 512] ld 512
        const float* B = pass ? B2 : B1;   // [512, N]   ld N
        for (int k0 = 0; k0 < K; k0 += 16) {
            #pragma unroll
            for (int t = 0; t < 4; ++t) {
                int i = tid + t * 256;
                As[i & 15][i >> 4] = A[(m0 + (i >> 4)) * K + k0 + (i & 15)];
            }
            #pragma unroll
            for (int t = 0; t < 4; ++t) {
                int i = tid + t * 256;
                Bs[i >> 6][i & 63] = B[(k0 + (i >> 6)) * N + n0 + (i & 63)];
            }
            __syncthreads();
            #pragma unroll
            for (int kk = 0; kk < 16; ++kk) {
                float4 av = *(const float4*)&As[kk][ty * 4];
                float4 bv = *(const float4*)&Bs[kk][tx * 4];
                float a[4] = {av.x, av.y, av.z, av.w};
                float b[4] = {bv.x, bv.y, bv.z, bv.w};
                #pragma unroll
                for (int p = 0; p < 4; ++p)
                    #pragma unroll
                    for (int q = 0; q < 4; ++q)
                        acc[p][q] += a[p] * b[q];
            }
            __syncthreads();
        }
    }

    #pragma unroll
    for (int p = 0; p < 4; ++p) {
        int m = m0 + ty * 4 + p;
        #pragma unroll
        for (int q = 0; q < 4; ++q) {
            int n = n0 + tx * 4 + q;
            C[m * N + n] = acc[p][q] + (add_bias ? bias[n] : 0.f);
        }
    }
}

__global__ void __launch_bounds__(256) phase1_kernel(
    const float* __restrict__ x,     const float* __restrict__ kernel,
    const float* __restrict__ h_tm1, const float* __restrict__ rec,
    const float* __restrict__ bias,  const float* __restrict__ w,
    const float* __restrict__ hebb,
    float* __restrict__ pre, float* __restrict__ hw, float* __restrict__ red4)
{
    __shared__ float smem[2048];   // 8KB: GEMM tiles, or reduce staging
    int bid = blockIdx.x;
    int tid = threadIdx.x;

    if (bid < 1024) {
        // ---- hebb partial reduce: red4[b,chunk,v] = sum over 128 u's ----
        int b     = bid >> 2;
        int chunk = bid & 3;
        int v4    = tid & 127;   // float4 column index (512 floats = 128 f4)
        int uh    = tid >> 7;    // 0/1: which 64-u half

        float* hs = smem;        // 128 h values for this chunk
        if (tid < 128) hs[tid] = h_tm1[b * Udim + chunk * 128 + tid];
        __syncthreads();

        const float4* p = (const float4*)(hebb
            + (size_t)b * Udim * Udim
            + (size_t)(chunk * 128 + uh * 64) * Udim) + v4;

        float4 acc = make_float4(0.f, 0.f, 0.f, 0.f);
        const float* hsl = hs + uh * 64;
        #pragma unroll 8
        for (int u = 0; u < 64; ++u) {
            float hv = hsl[u];
            float4 t = p[(size_t)u * 128];
            acc.x += hv * t.x; acc.y += hv * t.y;
            acc.z += hv * t.z; acc.w += hv * t.w;
        }
        __syncthreads();
        float4* st = (float4*)(smem + 128);
        if (uh == 1) st[v4] = acc;
        __syncthreads();
        if (uh == 0) {
            float4 o = st[v4];
            acc.x += o.x; acc.y += o.y; acc.z += o.z; acc.w += o.w;
            ((float4*)(red4 + (size_t)(b * 4 + chunk) * Udim))[v4] = acc;
        }
    } else if (bid < 1024 + 128) {
        // ---- gates GEMM: 32 n-tiles x 4 m-tiles ----
        int t  = bid - 1024;
        int n0 = (t & 31) * 64;
        int m0 = (t >> 5) * 64;
        bool do_rec = !(n0 >= 2 * Udim && n0 < 3 * Udim);  // skip rec on c-slice
        gemm64(x, kernel, h_tm1, rec, bias, pre, N4U, m0, n0, do_rec, true, smem);
    } else {
        // ---- hw GEMM: 8 n-tiles x 4 m-tiles ----
        int t  = bid - 1024 - 128;
        int n0 = (t & 7) * 64;
        int m0 = (t >> 3) * 64;
        gemm64(h_tm1, w, nullptr, nullptr, nullptr, hw, Udim, m0, n0, false, false, smem);
    }
}

// =======================================================================
// Phase 2: combine — gates, c, h, eta reduction, g   (256 blocks x 512)
// =======================================================================
__device__ __forceinline__ float hsig(float z) {
    return fminf(fmaxf(0.2f * z + 0.5f, 0.f), 1.f);
}

__global__ void __launch_bounds__(512) combine_kernel(
    const float* __restrict__ pre, const float* __restrict__ hw,
    const float* __restrict__ red4, const float* __restrict__ c_tm1,
    const float* __restrict__ alpha, const float* __restrict__ h2mod,
    const float* __restrict__ fanout,
    float* __restrict__ out, float* __restrict__ g)
{
    int b = blockIdx.x;
    int v = threadIdx.x;

    const float* r = red4 + (size_t)b * 4 * Udim;
    float red = r[v] + r[Udim + v] + r[2 * Udim + v] + r[3 * Udim + v];

    float xi = pre[b * N4U + v];
    float xf = pre[b * N4U + Udim + v];
    float xc = pre[b * N4U + 2 * Udim + v];
    float xo = pre[b * N4U + 3 * Udim + v];

    float gi = hsig(xi), gf = hsig(xf), go = hsig(xo);
    float itc = tanhf(xc + hw[b * Udim + v] + alpha[v] * red);
    float c = gf * c_tm1[b * Udim + v] + gi * itc;
    float h = go * tanhf(c);

    out[b * Udim + v] = h;
    out[Bdim * Udim + b * Udim + v] = c;

    // eta = tanh(sum_v h*h2mod[v]) via warp shuffles
    float s = h * h2mod[v];
    #pragma unroll
    for (int o = 16; o > 0; o >>= 1) s += __shfl_down_sync(0xffffffffu, s, o);
    __shared__ float ws[16];
    __shared__ float eta_s;
    if ((v & 31) == 0) ws[v >> 5] = s;
    __syncthreads();
    if (v < 16) {
        float t = ws[v];
        #pragma unroll
        for (int o = 8; o > 0; o >>= 1) t += __shfl_down_sync(0xffffu, t, o);
        if (v == 0) eta_s = tanhf(t);
    }
    __syncthreads();
    g[b * Udim + v] = eta_s * fanout[v] * itc;
}

// =======================================================================
// Phase 3: hebb update — reverse order so first reads hit L2 tail of pass 1
// =======================================================================
__global__ void __launch_bounds__(256) hebb_update(
    const float* __restrict__ hebb, const float* __restrict__ h_tm1,
    const float* __restrict__ g, float* __restrict__ out)
{
    const int TOTAL4 = Bdim * Udim * Udim / 4;             // 16,777,216
    int idx = TOTAL4 - 1 - (blockIdx.x * 256 + threadIdx.x);
    int row = idx >> 7;            // b*512 + u
    int v4  = idx & 127;
    int b   = row >> 9;

    float hu = h_tm1[row];
    float4 hv = ((const float4*)hebb)[idx];
    float4 gg = ((const float4*)(g + b * Udim))[v4];

    float4 r;
    r.x = fminf(fmaxf(hv.x + hu * gg.x, -2.f), 2.f);
    r.y = fminf(fmaxf(hv.y + hu * gg.y, -2.f), 2.f);
    r.z = fminf(fmaxf(hv.z + hu * gg.z, -2.f), 2.f);
    r.w = fminf(fmaxf(hv.w + hu * gg.w, -2.f), 2.f);
    ((float4*)out)[idx] = r;
}

// ---------------- launch ----------------
extern "C" void kernel_launch(void* const* d_in, const int* in_sizes, int n_in,
                              void* d_out, int out_size)
{
    const float* x      = (const float*)d_in[0];
    const float* h_tm1  = (const float*)d_in[1];
    const float* c_tm1  = (const float*)d_in[2];
    const float* hebb   = (const float*)d_in[3];
    const float* kernel = (const float*)d_in[4];
    const float* rec    = (const float*)d_in[5];
    const float* bias   = (const float*)d_in[6];
    const float* w      = (const float*)d_in[7];
    const float* alpha  = (const float*)d_in[8];
    const float* h2mod  = (const float*)d_in[9];
    const float* fanout = (const float*)d_in[10];
    float* out = (float*)d_out;

    float *pre, *hw, *red4, *gg;
    cudaGetSymbolAddress((void**)&pre,  g_pre);
    cudaGetSymbolAddress((void**)&hw,   g_hw);
    cudaGetSymbolAddress((void**)&red4, g_red4);
    cudaGetSymbolAddress((void**)&gg,   g_g);

    phase1_kernel<<<1024 + 128 + 32, 256>>>(x, kernel, h_tm1, rec, bias, w, hebb,
                                            pre, hw, red4);
    combine_kernel<<<Bdim, Udim>>>(pre, hw, red4, c_tm1, alpha, h2mod, fanout, out, gg);
    hebb_update<<<65536, 256>>>(hebb, h_tm1, gg, out + 2 * Bdim * Udim);
}

// round 3
// speedup vs baseline: 1.5117x; 1.5117x over previous
#include <cuda_runtime.h>
#include <cstdint>

#define Bdim 256
#define Udim 512
#define Ddim 512
#define N4U  2048

// ---------------- scratch ----------------
__device__ float g_pre [Bdim * N4U];        // gates pre-activations [B, 4U]
__device__ float g_hw  [Bdim * Udim];       // h_tm1 @ w
__device__ float g_red4[Bdim * 4 * Udim];   // partial hebb reductions (4 u-chunks)
__device__ float g_g   [Bdim * Udim];       // eta[b,v]*itc[b,v]

// =======================================================================
// Phase 1: one kernel, GEMM blocks FIRST so they co-reside with the
// DRAM-bound reduce blocks instead of running as an empty tail wave.
//   [0, 128)       : gates GEMM  pre = bias + x@kernel (+ h@rec except c-slice)
//   [128, 160)     : hw GEMM     hw = h_tm1 @ w
//   [160, 1184)    : hebb partial reduce  (b = t>>2, u-chunk = t&3)
// =======================================================================

__device__ __forceinline__ void gemm64(
    const float* __restrict__ A1, const float* __restrict__ B1,
    const float* __restrict__ A2, const float* __restrict__ B2,
    const float* __restrict__ bias, float* __restrict__ C,
    int N, int m0, int n0, bool do_rec, bool add_bias, float* smem)
{
    const int K = 512;
    float (*As)[64] = (float(*)[64])smem;          // 16x64
    float (*Bs)[64] = (float(*)[64])(smem + 1024); // 16x64

    int tid = threadIdx.x;
    int tx  = tid & 15;
    int ty  = tid >> 4;

    float acc[4][4];
    #pragma unroll
    for (int p = 0; p < 4; ++p)
        #pragma unroll
        for (int q = 0; q < 4; ++q) acc[p][q] = 0.f;

    int npass = do_rec ? 2 : 1;
    for (int pass = 0; pass < npass; ++pass) {
        const float* A = pass ? A2 : A1;   // [256, 512] ld 512
        const float* B = pass ? B2 : B1;   // [512, N]   ld N
        for (int k0 = 0; k0 < K; k0 += 16) {
            #pragma unroll
            for (int t = 0; t < 4; ++t) {
                int i = tid + t * 256;
                As[i & 15][i >> 4] = A[(m0 + (i >> 4)) * K + k0 + (i & 15)];
            }
            #pragma unroll
            for (int t = 0; t < 4; ++t) {
                int i = tid + t * 256;
                Bs[i >> 6][i & 63] = B[(k0 + (i >> 6)) * N + n0 + (i & 63)];
            }
            __syncthreads();
            #pragma unroll
            for (int kk = 0; kk < 16; ++kk) {
                float4 av = *(const float4*)&As[kk][ty * 4];
                float4 bv = *(const float4*)&Bs[kk][tx * 4];
                float a[4] = {av.x, av.y, av.z, av.w};
                float b[4] = {bv.x, bv.y, bv.z, bv.w};
                #pragma unroll
                for (int p = 0; p < 4; ++p)
                    #pragma unroll
                    for (int q = 0; q < 4; ++q)
                        acc[p][q] += a[p] * b[q];
            }
            __syncthreads();
        }
    }

    #pragma unroll
    for (int p = 0; p < 4; ++p) {
        int m = m0 + ty * 4 + p;
        #pragma unroll
        for (int q = 0; q < 4; ++q) {
            int n = n0 + tx * 4 + q;
            C[m * N + n] = acc[p][q] + (add_bias ? bias[n] : 0.f);
        }
    }
}

__global__ void __launch_bounds__(256) phase1_kernel(
    const float* __restrict__ x,     const float* __restrict__ kernel,
    const float* __restrict__ h_tm1, const float* __restrict__ rec,
    const float* __restrict__ bias,  const float* __restrict__ w,
    const float* __restrict__ hebb,
    float* __restrict__ pre, float* __restrict__ hw, float* __restrict__ red4)
{
    __shared__ float smem[2048];   // 8KB
    int bid = blockIdx.x;
    int tid = threadIdx.x;

    if (bid < 128) {
        // ---- gates GEMM: 32 n-tiles x 4 m-tiles ----
        int n0 = (bid & 31) * 64;
        int m0 = (bid >> 5) * 64;
        bool do_rec = !(n0 >= 2 * Udim && n0 < 3 * Udim);  // skip rec on c-slice
        gemm64(x, kernel, h_tm1, rec, bias, pre, N4U, m0, n0, do_rec, true, smem);
    } else if (bid < 160) {
        // ---- hw GEMM: 8 n-tiles x 4 m-tiles ----
        int t  = bid - 128;
        int n0 = (t & 7) * 64;
        int m0 = (t >> 3) * 64;
        gemm64(h_tm1, w, nullptr, nullptr, nullptr, hw, Udim, m0, n0, false, false, smem);
    } else {
        // ---- hebb partial reduce: red4[b,chunk,v] = sum over 128 u's ----
        int t     = bid - 160;
        int b     = t >> 2;
        int chunk = t & 3;
        int v4    = tid & 127;   // float4 column index (512 floats = 128 f4)
        int uh    = tid >> 7;    // 0/1: which 64-u half

        float* hs = smem;        // 128 h values for this chunk
        if (tid < 128) hs[tid] = h_tm1[b * Udim + chunk * 128 + tid];
        __syncthreads();

        const float4* p = (const float4*)(hebb
            + (size_t)b * Udim * Udim
            + (size_t)(chunk * 128 + uh * 64) * Udim) + v4;

        float4 acc = make_float4(0.f, 0.f, 0.f, 0.f);
        const float* hsl = hs + uh * 64;
        #pragma unroll 8
        for (int u = 0; u < 64; ++u) {
            float hv = hsl[u];
            float4 tt = __ldcs(&p[(size_t)u * 128]);
            acc.x += hv * tt.x; acc.y += hv * tt.y;
            acc.z += hv * tt.z; acc.w += hv * tt.w;
        }
        __syncthreads();
        float4* st = (float4*)(smem + 128);
        if (uh == 1) st[v4] = acc;
        __syncthreads();
        if (uh == 0) {
            float4 o = st[v4];
            acc.x += o.x; acc.y += o.y; acc.z += o.z; acc.w += o.w;
            ((float4*)(red4 + (size_t)(b * 4 + chunk) * Udim))[v4] = acc;
        }
    }
}

// =======================================================================
// Phase 2: combine — gates, c, h, eta reduction, g   (256 blocks x 512)
// =======================================================================
__device__ __forceinline__ float hsig(float z) {
    return fminf(fmaxf(0.2f * z + 0.5f, 0.f), 1.f);
}

__global__ void __launch_bounds__(512) combine_kernel(
    const float* __restrict__ pre, const float* __restrict__ hw,
    const float* __restrict__ red4, const float* __restrict__ c_tm1,
    const float* __restrict__ alpha, const float* __restrict__ h2mod,
    const float* __restrict__ fanout,
    float* __restrict__ out, float* __restrict__ g)
{
    int b = blockIdx.x;
    int v = threadIdx.x;

    const float* r = red4 + (size_t)b * 4 * Udim;
    float red = (r[v] + r[Udim + v]) + (r[2 * Udim + v] + r[3 * Udim + v]);

    float xi = pre[b * N4U + v];
    float xf = pre[b * N4U + Udim + v];
    float xc = pre[b * N4U + 2 * Udim + v];
    float xo = pre[b * N4U + 3 * Udim + v];

    float gi = hsig(xi), gf = hsig(xf), go = hsig(xo);
    float itc = tanhf(xc + hw[b * Udim + v] + alpha[v] * red);
    float c = gf * c_tm1[b * Udim + v] + gi * itc;
    float h = go * tanhf(c);

    out[b * Udim + v] = h;
    out[Bdim * Udim + b * Udim + v] = c;

    // eta = tanh(sum_v h*h2mod[v]) via warp shuffles
    float s = h * h2mod[v];
    #pragma unroll
    for (int o = 16; o > 0; o >>= 1) s += __shfl_down_sync(0xffffffffu, s, o);
    __shared__ float ws[16];
    __shared__ float eta_s;
    if ((v & 31) == 0) ws[v >> 5] = s;
    __syncthreads();
    if (v < 16) {
        float t = ws[v];
        #pragma unroll
        for (int o = 8; o > 0; o >>= 1) t += __shfl_down_sync(0xffffu, t, o);
        if (v == 0) eta_s = tanhf(t);
    }
    __syncthreads();
    g[b * Udim + v] = eta_s * fanout[v] * itc;
}

// =======================================================================
// Phase 3: hebb update — 4 independent float4 per thread, streaming hints
// =======================================================================
__global__ void __launch_bounds__(256) hebb_update(
    const float* __restrict__ hebb, const float* __restrict__ h_tm1,
    const float* __restrict__ g, float* __restrict__ out)
{
    // TOTAL4 = 16,777,216 float4s; 16384 blocks x 256 threads x 4 f4
    int base = blockIdx.x * 1024 + threadIdx.x;

    #pragma unroll
    for (int k = 0; k < 4; ++k) {
        int idx = base + k * 256;
        int row = idx >> 7;            // b*512 + u
        int v4  = idx & 127;
        int b   = idx >> 16;           // 65536 f4 per batch sample

        float hu = h_tm1[row];
        float4 hv = __ldcs(((const float4*)hebb) + idx);
        float4 gg = ((const float4*)(g + b * Udim))[v4];

        float4 r;
        r.x = fminf(fmaxf(hv.x + hu * gg.x, -2.f), 2.f);
        r.y = fminf(fmaxf(hv.y + hu * gg.y, -2.f), 2.f);
        r.z = fminf(fmaxf(hv.z + hu * gg.z, -2.f), 2.f);
        r.w = fminf(fmaxf(hv.w + hu * gg.w, -2.f), 2.f);
        __stcs(((float4*)out) + idx, r);
    }
}

// ---------------- launch ----------------
extern "C" void kernel_launch(void* const* d_in, const int* in_sizes, int n_in,
                              void* d_out, int out_size)
{
    const float* x      = (const float*)d_in[0];
    const float* h_tm1  = (const float*)d_in[1];
    const float* c_tm1  = (const float*)d_in[2];
    const float* hebb   = (const float*)d_in[3];
    const float* kernel = (const float*)d_in[4];
    const float* rec    = (const float*)d_in[5];
    const float* bias   = (const float*)d_in[6];
    const float* w      = (const float*)d_in[7];
    const float* alpha  = (const float*)d_in[8];
    const float* h2mod  = (const float*)d_in[9];
    const float* fanout = (const float*)d_in[10];
    float* out = (float*)d_out;

    float *pre, *hw, *red4, *gg;
    cudaGetSymbolAddress((void**)&pre,  g_pre);
    cudaGetSymbolAddress((void**)&hw,   g_hw);
    cudaGetSymbolAddress((void**)&red4, g_red4);
    cudaGetSymbolAddress((void**)&gg,   g_g);

    phase1_kernel<<<160 + 1024, 256>>>(x, kernel, h_tm1, rec, bias, w, hebb,
                                       pre, hw, red4);
    combine_kernel<<<Bdim, Udim>>>(pre, hw, red4, c_tm1, alpha, h2mod, fanout, out, gg);
    hebb_update<<<16384, 256>>>(hebb, h_tm1, gg, out + 2 * Bdim * Udim);
}

// round 4
// speedup vs baseline: 1.5631x; 1.0340x over previous
#include <cuda_runtime.h>
#include <cstdint>

#define Bdim 256
#define Udim 512
#define Ddim 512
#define N4U  2048

typedef unsigned long long ull;

// ---------------- scratch ----------------
__device__ float g_pre [Bdim * N4U];        // gates pre-activations [B, 4U]
__device__ float g_hw  [Bdim * Udim];       // h_tm1 @ w
__device__ float g_red4[Bdim * 4 * Udim];   // partial hebb reductions (4 u-chunks)
__device__ float g_g   [Bdim * Udim];       // eta[b,v]*itc[b,v]

// ---------------- packed f32x2 helpers ----------------
__device__ __forceinline__ ull pk2(float x, float y) {
    ull r; asm("mov.b64 %0, {%1, %2};" : "=l"(r) : "f"(x), "f"(y)); return r;
}
__device__ __forceinline__ ull fma2(ull a, ull b, ull c) {
    ull d; asm("fma.rn.f32x2 %0, %1, %2, %3;" : "=l"(d) : "l"(a), "l"(b), "l"(c)); return d;
}
__device__ __forceinline__ float2 upk(ull v) {
    float2 r; asm("mov.b64 {%0, %1}, %2;" : "=f"(r.x), "=f"(r.y) : "l"(v)); return r;
}

// =======================================================================
// Phase 1: one kernel, GEMM blocks first (co-reside with DRAM-bound reduce)
//   [0, 256)    : gates GEMM, 32x64 tiles: pre = bias + x@kernel (+h@rec, not c-slice)
//   [256, 320)  : hw GEMM,    32x64 tiles: hw = h_tm1 @ w
//   [320, 1344) : hebb partial reduce (b = t>>2, 128-u chunk = t&3)
// =======================================================================

// 32x64 tile GEMM, 256 threads, 2x4 per thread, FFMA2 inner loop.
__device__ __forceinline__ void gemm32x64(
    const float* __restrict__ A1, const float* __restrict__ B1,
    const float* __restrict__ A2, const float* __restrict__ B2,
    const float* __restrict__ bias, float* __restrict__ C,
    int N, int m0, int n0, bool do_rec, bool add_bias, float* smem)
{
    const int K = 512;
    float (*As)[32] = (float(*)[32])smem;         // 16 x 32
    float (*Bs)[64] = (float(*)[64])(smem + 512); // 16 x 64

    int tid = threadIdx.x;
    int tx  = tid & 15;    // n-group: 4 cols
    int ty  = tid >> 4;    // m-group: 2 rows

    ull acc[2][2];
    acc[0][0] = acc[0][1] = acc[1][0] = acc[1][1] = 0ull;

    int npass = do_rec ? 2 : 1;
    for (int pass = 0; pass < npass; ++pass) {
        const float* A = pass ? A2 : A1;   // [256, 512] ld 512
        const float* B = pass ? B2 : B1;   // [512, N]   ld N
        for (int k0 = 0; k0 < K; k0 += 16) {
            #pragma unroll
            for (int t = 0; t < 2; ++t) {
                int i = tid + t * 256;     // 512 elems
                As[i & 15][i >> 4] = A[(m0 + (i >> 4)) * K + k0 + (i & 15)];
            }
            #pragma unroll
            for (int t = 0; t < 4; ++t) {
                int i = tid + t * 256;     // 1024 elems
                Bs[i >> 6][i & 63] = B[(k0 + (i >> 6)) * N + n0 + (i & 63)];
            }
            __syncthreads();
            #pragma unroll
            for (int kk = 0; kk < 16; ++kk) {
                float2 av = *(const float2*)&As[kk][ty * 2];
                ulonglong2 bv = *(const ulonglong2*)&Bs[kk][tx * 4];
                ull a0 = pk2(av.x, av.x);
                ull a1 = pk2(av.y, av.y);
                acc[0][0] = fma2(a0, bv.x, acc[0][0]);
                acc[0][1] = fma2(a0, bv.y, acc[0][1]);
                acc[1][0] = fma2(a1, bv.x, acc[1][0]);
                acc[1][1] = fma2(a1, bv.y, acc[1][1]);
            }
            __syncthreads();
        }
    }

    int n = n0 + tx * 4;
    float b0 = 0.f, b1 = 0.f, b2 = 0.f, b3 = 0.f;
    if (add_bias) { b0 = bias[n]; b1 = bias[n+1]; b2 = bias[n+2]; b3 = bias[n+3]; }
    #pragma unroll
    for (int r = 0; r < 2; ++r) {
        int m = m0 + ty * 2 + r;
        float2 lo = upk(acc[r][0]);
        float2 hi = upk(acc[r][1]);
        float4 o = make_float4(lo.x + b0, lo.y + b1, hi.x + b2, hi.y + b3);
        *(float4*)&C[m * N + n] = o;
    }
}

__global__ void __launch_bounds__(256) phase1_kernel(
    const float* __restrict__ x,     const float* __restrict__ kernel,
    const float* __restrict__ h_tm1, const float* __restrict__ rec,
    const float* __restrict__ bias,  const float* __restrict__ w,
    const float* __restrict__ hebb,
    float* __restrict__ pre, float* __restrict__ hw, float* __restrict__ red4)
{
    __shared__ __align__(16) float smem[1536];   // 6KB
    int bid = blockIdx.x;
    int tid = threadIdx.x;

    if (bid < 256) {
        // ---- gates GEMM: 32 n-tiles x 8 m-tiles ----
        int n0 = (bid & 31) * 64;
        int m0 = (bid >> 5) * 32;
        bool do_rec = !(n0 >= 2 * Udim && n0 < 3 * Udim);  // c-slice: no rec
        gemm32x64(x, kernel, h_tm1, rec, bias, pre, N4U, m0, n0, do_rec, true, smem);
    } else if (bid < 320) {
        // ---- hw GEMM: 8 n-tiles x 8 m-tiles ----
        int t  = bid - 256;
        int n0 = (t & 7) * 64;
        int m0 = (t >> 3) * 32;
        gemm32x64(h_tm1, w, nullptr, nullptr, nullptr, hw, Udim, m0, n0, false, false, smem);
    } else {
        // ---- hebb partial reduce: red4[b,chunk,v] = sum over 128 u's ----
        int t     = bid - 320;
        int b     = t >> 2;
        int chunk = t & 3;
        int v4    = tid & 127;   // float4 column (512 floats = 128 f4)
        int uh    = tid >> 7;    // which 64-u half

        ull* hs2 = (ull*)smem;   // 128 duplicated h values (1KB)
        if (tid < 128) {
            float hv = h_tm1[b * Udim + chunk * 128 + tid];
            hs2[tid] = pk2(hv, hv);
        }
        __syncthreads();

        const float4* p = (const float4*)(hebb
            + (size_t)b * Udim * Udim
            + (size_t)(chunk * 128 + uh * 64) * Udim) + v4;

        ull acc0 = 0ull, acc1 = 0ull;
        const ull* hsl = hs2 + uh * 64;
        #pragma unroll 8
        for (int u = 0; u < 64; ++u) {
            ull hd = hsl[u];
            float4 tt = __ldcs(&p[(size_t)u * 128]);
            ulonglong2 tv = *(ulonglong2*)&tt;
            acc0 = fma2(hd, tv.x, acc0);
            acc1 = fma2(hd, tv.y, acc1);
        }
        float2 r01 = upk(acc0);
        float2 r23 = upk(acc1);
        float4 acc = make_float4(r01.x, r01.y, r23.x, r23.y);

        __syncthreads();
        float4* st = (float4*)(smem + 256);
        if (uh == 1) st[v4] = acc;
        __syncthreads();
        if (uh == 0) {
            float4 o = st[v4];
            acc.x += o.x; acc.y += o.y; acc.z += o.z; acc.w += o.w;
            ((float4*)(red4 + (size_t)(b * 4 + chunk) * Udim))[v4] = acc;
        }
    }
}

// =======================================================================
// Phase 2: combine — gates, c, h, eta reduction, g   (256 blocks x 512)
// =======================================================================
__device__ __forceinline__ float hsig(float z) {
    return fminf(fmaxf(0.2f * z + 0.5f, 0.f), 1.f);
}

__global__ void __launch_bounds__(512) combine_kernel(
    const float* __restrict__ pre, const float* __restrict__ hw,
    const float* __restrict__ red4, const float* __restrict__ c_tm1,
    const float* __restrict__ alpha, const float* __restrict__ h2mod,
    const float* __restrict__ fanout,
    float* __restrict__ out, float* __restrict__ g)
{
    int b = blockIdx.x;
    int v = threadIdx.x;

    const float* r = red4 + (size_t)b * 4 * Udim;
    float red = (r[v] + r[Udim + v]) + (r[2 * Udim + v] + r[3 * Udim + v]);

    float xi = pre[b * N4U + v];
    float xf = pre[b * N4U + Udim + v];
    float xc = pre[b * N4U + 2 * Udim + v];
    float xo = pre[b * N4U + 3 * Udim + v];

    float gi = hsig(xi), gf = hsig(xf), go = hsig(xo);
    float itc = tanhf(xc + hw[b * Udim + v] + alpha[v] * red);
    float c = gf * c_tm1[b * Udim + v] + gi * itc;
    float h = go * tanhf(c);

    out[b * Udim + v] = h;
    out[Bdim * Udim + b * Udim + v] = c;

    // eta = tanh(sum_v h*h2mod[v]) via warp shuffles
    float s = h * h2mod[v];
    #pragma unroll
    for (int o = 16; o > 0; o >>= 1) s += __shfl_down_sync(0xffffffffu, s, o);
    __shared__ float ws[16];
    __shared__ float eta_s;
    if ((v & 31) == 0) ws[v >> 5] = s;
    __syncthreads();
    if (v < 16) {
        float t = ws[v];
        #pragma unroll
        for (int o = 8; o > 0; o >>= 1) t += __shfl_down_sync(0xffffu, t, o);
        if (v == 0) eta_s = tanhf(t);
    }
    __syncthreads();
    g[b * Udim + v] = eta_s * fanout[v] * itc;
}

// =======================================================================
// Phase 3: hebb update — 4 independent float4 per thread, streaming hints
// =======================================================================
__global__ void __launch_bounds__(256) hebb_update(
    const float* __restrict__ hebb, const float* __restrict__ h_tm1,
    const float* __restrict__ g, float* __restrict__ out)
{
    int base = blockIdx.x * 1024 + threadIdx.x;

    #pragma unroll
    for (int k = 0; k < 4; ++k) {
        int idx = base + k * 256;
        int row = idx >> 7;            // b*512 + u
        int v4  = idx & 127;
        int b   = idx >> 16;           // 65536 f4 per batch sample

        float hu = h_tm1[row];
        float4 hv = __ldcs(((const float4*)hebb) + idx);
        float4 gg = ((const float4*)(g + b * Udim))[v4];

        float4 r;
        r.x = fminf(fmaxf(hv.x + hu * gg.x, -2.f), 2.f);
        r.y = fminf(fmaxf(hv.y + hu * gg.y, -2.f), 2.f);
        r.z = fminf(fmaxf(hv.z + hu * gg.z, -2.f), 2.f);
        r.w = fminf(fmaxf(hv.w + hu * gg.w, -2.f), 2.f);
        __stcs(((float4*)out) + idx, r);
    }
}

// ---------------- launch ----------------
extern "C" void kernel_launch(void* const* d_in, const int* in_sizes, int n_in,
                              void* d_out, int out_size)
{
    const float* x      = (const float*)d_in[0];
    const float* h_tm1  = (const float*)d_in[1];
    const float* c_tm1  = (const float*)d_in[2];
    const float* hebb   = (const float*)d_in[3];
    const float* kernel = (const float*)d_in[4];
    const float* rec    = (const float*)d_in[5];
    const float* bias   = (const float*)d_in[6];
    const float* w      = (const float*)d_in[7];
    const float* alpha  = (const float*)d_in[8];
    const float* h2mod  = (const float*)d_in[9];
    const float* fanout = (const float*)d_in[10];
    float* out = (float*)d_out;

    float *pre, *hw, *red4, *gg;
    cudaGetSymbolAddress((void**)&pre,  g_pre);
    cudaGetSymbolAddress((void**)&hw,   g_hw);
    cudaGetSymbolAddress((void**)&red4, g_red4);
    cudaGetSymbolAddress((void**)&gg,   g_g);

    phase1_kernel<<<320 + 1024, 256>>>(x, kernel, h_tm1, rec, bias, w, hebb,
                                       pre, hw, red4);
    combine_kernel<<<Bdim, Udim>>>(pre, hw, red4, c_tm1, alpha, h2mod, fanout, out, gg);
    hebb_update<<<16384, 256>>>(hebb, h_tm1, gg, out + 2 * Bdim * Udim);
}